// round 1
// baseline (speedup 1.0000x reference)
#include <cuda_runtime.h>

// Problem constants (fixed by setup_inputs)
constexpr int B  = 4;
constexpr int C  = 32;
constexpr int H  = 512;
constexpr int W  = 960;
constexpr int TS = 4;
constexpr int Ht = H / TS;   // 128
constexpr int Wt = W / TS;   // 240
constexpr int HW = H * W;
constexpr int BX = 160;      // 5 warps, 960 = 6*160 exact

__global__ __launch_bounds__(BX)
void tile_warp_cost_kernel(const float* __restrict__ tile_plane,
                           const float* __restrict__ fea_l,
                           const float* __restrict__ fea_r,
                           float* __restrict__ out)
{
    const int x = blockIdx.x * BX + threadIdx.x;   // 0..959
    const int y = blockIdx.y;                      // 0..511
    const int b = blockIdx.z;                      // 0..3

    const int ty = y >> 2, tx = x >> 2;
    const int iy = y & 3,  jx = x & 3;

    // tile_plane layout [B, 3, Ht, Wt]
    const int tbase = b * 3 * Ht * Wt + ty * Wt + tx;
    const float d   = __ldg(tile_plane + tbase);
    const float ddx = __ldg(tile_plane + tbase + Ht * Wt);
    const float ddy = __ldg(tile_plane + tbase + 2 * Ht * Wt);

    // slanted-plane disparity at full res (disp_d = 0 hypothesis)
    const float disp0 = d + ((float)iy - 1.5f) * ddy + ((float)jx - 1.5f) * ddx;
    const float xs0   = (float)x - disp0;     // source x for disp_d = 0
    const float xf    = floorf(xs0);
    const float w     = xs0 - xf;             // shared interp weight for all 3 hypotheses
    const int   x00   = (int)xf;

    // 4 consecutive (clamped) fea_r sample columns shared by all hypotheses
    const int j0 = min(max(x00 - 1, 0), W - 1);
    const int j1 = min(max(x00,     0), W - 1);
    const int j2 = min(max(x00 + 1, 0), W - 1);
    const int j3 = min(max(x00 + 2, 0), W - 1);

    // validity per hypothesis: disp_d=-1 -> x_src = xs0+1 ; 0 -> xs0 ; +1 -> xs0-1
    const float xsM = xs0 + 1.0f;   // disp_d = -1  (uses j2,j3)
    const float xsP = xs0 - 1.0f;   // disp_d = +1  (uses j0,j1)
    const bool vM = (xsM >= 0.0f) && (xsM <= (float)(W - 1));
    const bool v0 = (xs0 >= 0.0f) && (xs0 <= (float)(W - 1));
    const bool vP = (xsP >= 0.0f) && (xsP <= (float)(W - 1));

    float cM = 0.0f, c0 = 0.0f, cP = 0.0f;

    int base = (b * C * H + y) * W;   // row offset for channel 0 (fits in int32)

    #pragma unroll 8
    for (int c = 0; c < C; ++c) {
        const float fl = __ldg(fea_l + base + x);
        const float r0 = __ldg(fea_r + base + j0);
        const float r1 = __ldg(fea_r + base + j1);
        const float r2 = __ldg(fea_r + base + j2);
        const float r3 = __ldg(fea_r + base + j3);

        // f0*(1-w) + f1*w  ==  f0 + w*(f1-f0)
        const float wP = r0 + w * (r1 - r0);   // disp_d = +1
        const float w0 = r1 + w * (r2 - r1);   // disp_d =  0
        const float wM = r2 + w * (r3 - r2);   // disp_d = -1

        cM += fabsf(fl - (vM ? wM : 0.0f));
        c0 += fabsf(fl - (v0 ? w0 : 0.0f));
        cP += fabsf(fl - (vP ? wP : 0.0f));

        base += HW;
    }

    // output [B, 48, Ht, Wt]; channel = vblock*16 + iy*4 + jx; vblock order: -1, 0, +1
    const int chsp  = (iy * 4 + jx) * (Ht * Wt);
    const int obase = b * 48 * Ht * Wt + ty * Wt + tx;
    out[obase + chsp]                   = cM;   // disp_d = -1
    out[obase + 16 * Ht * Wt + chsp]    = c0;   // disp_d =  0
    out[obase + 32 * Ht * Wt + chsp]    = cP;   // disp_d = +1
}

extern "C" void kernel_launch(void* const* d_in, const int* in_sizes, int n_in,
                              void* d_out, int out_size)
{
    const float* tile_plane = (const float*)d_in[0];
    const float* fea_l      = (const float*)d_in[1];
    const float* fea_r      = (const float*)d_in[2];
    float*       out        = (float*)d_out;

    dim3 grid(W / BX, H, B);   // (6, 512, 4)
    dim3 block(BX);
    tile_warp_cost_kernel<<<grid, block>>>(tile_plane, fea_l, fea_r, out);
}